// round 1
// baseline (speedup 1.0000x reference)
#include <cuda_runtime.h>
#include <math.h>

#define H 1024
#define V 50257
#define L 512

// ---------------- scratch (device globals; no allocations allowed) ----------
__device__ float g_scores[L];
__device__ float g_attnw[L];
__device__ float g_attn_partial[4][H];   // deterministic partial sums over L-chunks
__device__ float g_gru_in[H];
__device__ float g_gates[6 * H];         // [0,3H) = gx, [3H,6H) = gh
__device__ float g_hnew[H];
__device__ float g_logits[V];
__device__ float g_pm[64], g_ps[64];     // per-block (max, sumexp) partials
__device__ float g_lse;

__device__ __forceinline__ float warp_reduce_sum(float v) {
#pragma unroll
    for (int o = 16; o; o >>= 1) v += __shfl_down_sync(0xffffffffu, v, o);
    return v;
}

// ---------------- 1) attention scores: scores = attn_W @ [emb[x]; h0] + b ---
// 64 blocks x 256 threads, warp-per-row (512 rows, row length 2048)
__global__ void k_attn_gemv(const int* __restrict__ x,
                            const float* __restrict__ emb,
                            const float* __restrict__ hidden,
                            const float* __restrict__ attn_W,
                            const float* __restrict__ attn_b) {
    __shared__ float s[2 * H];
    const float* er = emb + (size_t)x[0] * H;
    for (int i = threadIdx.x; i < H; i += 256) {
        s[i] = er[i];
        s[H + i] = hidden[i];
    }
    __syncthreads();
    const int warp = threadIdx.x >> 5, lane = threadIdx.x & 31;
    const int row = blockIdx.x * 8 + warp;
    const float4* Wr = (const float4*)(attn_W + (size_t)row * (2 * H));
    const float4* sv = (const float4*)s;
    float acc = 0.f;
#pragma unroll
    for (int i = 0; i < 16; i++) {
        float4 w = Wr[lane + i * 32];
        float4 v = sv[lane + i * 32];
        acc += w.x * v.x + w.y * v.y + w.z * v.z + w.w * v.w;
    }
    acc = warp_reduce_sum(acc);
    if (lane == 0) g_scores[row] = acc + attn_b[row];
}

// ---------------- 2) softmax over 512 scores; also writes attn_weights out --
__global__ void k_softmax(float* __restrict__ out_attnw) {
    __shared__ float red[L];
    const int t = threadIdx.x;
    float v = g_scores[t];
    red[t] = v;
    __syncthreads();
    for (int o = 256; o; o >>= 1) {
        if (t < o) red[t] = fmaxf(red[t], red[t + o]);
        __syncthreads();
    }
    const float m = red[0];
    __syncthreads();
    float e = expf(v - m);
    red[t] = e;
    __syncthreads();
    for (int o = 256; o; o >>= 1) {
        if (t < o) red[t] += red[t + o];
        __syncthreads();
    }
    float w = e / red[0];
    g_attnw[t] = w;
    out_attnw[t] = w;
}

// ---------------- 3) attn_applied partials: grid(8 col-tiles, 4 L-chunks) ---
__global__ void k_attn_apply(const float* __restrict__ enc) {
    __shared__ float sw[128];
    const int j = blockIdx.x * 128 + threadIdx.x;
    const int l0 = blockIdx.y * 128;
    sw[threadIdx.x] = g_attnw[l0 + threadIdx.x];
    __syncthreads();
    float acc = 0.f;
#pragma unroll 8
    for (int l = 0; l < 128; l++)
        acc += sw[l] * enc[(size_t)(l0 + l) * H + j];
    g_attn_partial[blockIdx.y][j] = acc;
}

// ---------------- 4) combine + relu: gru_in = relu(comb_W @ [emb;attn] + b) -
// 128 blocks x 256 threads, warp-per-row (1024 rows x 2048)
__global__ void k_combine_relu(const int* __restrict__ x,
                               const float* __restrict__ emb,
                               const float* __restrict__ comb_W,
                               const float* __restrict__ comb_b) {
    __shared__ float s[2 * H];
    const float* er = emb + (size_t)x[0] * H;
    for (int i = threadIdx.x; i < H; i += 256) {
        s[i] = er[i];
        s[H + i] = g_attn_partial[0][i] + g_attn_partial[1][i] +
                   g_attn_partial[2][i] + g_attn_partial[3][i];
    }
    __syncthreads();
    const int warp = threadIdx.x >> 5, lane = threadIdx.x & 31;
    const int row = blockIdx.x * 8 + warp;
    const float4* Wr = (const float4*)(comb_W + (size_t)row * (2 * H));
    const float4* sv = (const float4*)s;
    float acc = 0.f;
#pragma unroll
    for (int i = 0; i < 16; i++) {
        float4 w = Wr[lane + i * 32];
        float4 v = sv[lane + i * 32];
        acc += w.x * v.x + w.y * v.y + w.z * v.z + w.w * v.w;
    }
    acc = warp_reduce_sum(acc);
    if (lane == 0) g_gru_in[row] = fmaxf(acc + comb_b[row], 0.f);
}

// ---------------- 5) GRU gate GEMVs: 6144 rows x 1024 ----------------------
// blocks 0..383 -> W_ih @ gru_in ; blocks 384..767 -> W_hh @ h0
__global__ void k_gates_gemv(const float* __restrict__ hidden,
                             const float* __restrict__ W_ih,
                             const float* __restrict__ W_hh,
                             const float* __restrict__ b_ih,
                             const float* __restrict__ b_hh) {
    __shared__ float s[H];
    const int base = blockIdx.x * 8;
    const bool is_ih = base < 3 * H;
    const float* vec = is_ih ? g_gru_in : hidden;
    for (int i = threadIdx.x; i < H; i += 256) s[i] = vec[i];
    __syncthreads();
    const int warp = threadIdx.x >> 5, lane = threadIdx.x & 31;
    const int row = base + warp;                    // 0..6143
    const int r = is_ih ? row : row - 3 * H;        // row within the matrix
    const float* W = is_ih ? W_ih : W_hh;
    const float* b = is_ih ? b_ih : b_hh;
    const float4* Wr = (const float4*)(W + (size_t)r * H);
    const float4* sv = (const float4*)s;
    float acc = 0.f;
#pragma unroll
    for (int i = 0; i < 8; i++) {
        float4 w = Wr[lane + i * 32];
        float4 v = sv[lane + i * 32];
        acc += w.x * v.x + w.y * v.y + w.z * v.z + w.w * v.w;
    }
    acc = warp_reduce_sum(acc);
    if (lane == 0) g_gates[row] = acc + b[r];
}

// ---------------- 6) GRU elementwise gate math ------------------------------
__global__ void k_gru(const float* __restrict__ hidden) {
    const int i = blockIdx.x * 256 + threadIdx.x;
    const float gxr = g_gates[i],            ghr = g_gates[3 * H + i];
    const float gxz = g_gates[H + i],        ghz = g_gates[4 * H + i];
    const float gxn = g_gates[2 * H + i],    ghn = g_gates[5 * H + i];
    const float r = 1.f / (1.f + expf(-(gxr + ghr)));
    const float z = 1.f / (1.f + expf(-(gxz + ghz)));
    const float n = tanhf(gxn + r * ghn);
    g_hnew[i] = (1.f - z) * n + z * hidden[i];
}

// ---------------- 7) THE big GEMV: logits = out_W @ h_new + out_b ----------
// warp-per-row, 8 rows/block, float4 streaming of 206 MB
__global__ void k_out_gemv(const float* __restrict__ out_W,
                           const float* __restrict__ out_b) {
    __shared__ float s[H];
    for (int i = threadIdx.x; i < H; i += 256) s[i] = g_hnew[i];
    __syncthreads();
    const int warp = threadIdx.x >> 5, lane = threadIdx.x & 31;
    const int row = blockIdx.x * 8 + warp;
    if (row >= V) return;
    const float4* Wr = (const float4*)(out_W + (size_t)row * H);
    const float4* sv = (const float4*)s;
    float acc = 0.f;
#pragma unroll
    for (int i = 0; i < 8; i++) {
        float4 w = Wr[lane + i * 32];
        float4 v = sv[lane + i * 32];
        acc += w.x * v.x + w.y * v.y + w.z * v.z + w.w * v.w;
    }
    acc = warp_reduce_sum(acc);
    if (lane == 0) g_logits[row] = acc + out_b[row];
}

// ---------------- 8) log-sum-exp partials (online max+sum, deterministic) --
__global__ void k_lse_part() {
    __shared__ float sm[256], ss[256];
    const int t = threadIdx.x;
    const int g0 = blockIdx.x * 256 + t;
    float m = -INFINITY, s = 0.f;
    for (int v = g0; v < V; v += 64 * 256) {
        const float xv = g_logits[v];
        const float nm = fmaxf(m, xv);
        s = s * expf(m - nm) + expf(xv - nm);
        m = nm;
    }
    sm[t] = m; ss[t] = s;
    __syncthreads();
    for (int o = 128; o; o >>= 1) {
        if (t < o) {
            const float m2 = sm[t + o], s2 = ss[t + o];
            const float nm = fmaxf(sm[t], m2);
            ss[t] = ss[t] * expf(sm[t] - nm) + s2 * expf(m2 - nm);
            sm[t] = nm;
        }
        __syncthreads();
    }
    if (t == 0) { g_pm[blockIdx.x] = sm[0]; g_ps[blockIdx.x] = ss[0]; }
}

__global__ void k_lse_comb() {
    __shared__ float sm[64], ss[64];
    const int t = threadIdx.x;
    sm[t] = g_pm[t]; ss[t] = g_ps[t];
    __syncthreads();
    for (int o = 32; o; o >>= 1) {
        if (t < o) {
            const float m2 = sm[t + o], s2 = ss[t + o];
            const float nm = fmaxf(sm[t], m2);
            ss[t] = ss[t] * expf(sm[t] - nm) + s2 * expf(m2 - nm);
            sm[t] = nm;
        }
        __syncthreads();
    }
    if (t == 0) g_lse = sm[0] + logf(ss[0]);
}

// ---------------- 9) write log-probs -----------------------------------------
__global__ void k_write_logp(float* __restrict__ out) {
    const float lse = g_lse;
    for (int v = blockIdx.x * 256 + threadIdx.x; v < V; v += gridDim.x * 256)
        out[v] = g_logits[v] - lse;
}

extern "C" void kernel_launch(void* const* d_in, const int* in_sizes, int n_in,
                              void* d_out, int out_size) {
    const int*   x      = (const int*)  d_in[0];
    const float* enc    = (const float*)d_in[1];
    const float* hidden = (const float*)d_in[2];
    const float* emb    = (const float*)d_in[3];
    const float* attn_W = (const float*)d_in[4];
    const float* attn_b = (const float*)d_in[5];
    const float* comb_W = (const float*)d_in[6];
    const float* comb_b = (const float*)d_in[7];
    const float* W_ih   = (const float*)d_in[8];
    const float* W_hh   = (const float*)d_in[9];
    const float* b_ih   = (const float*)d_in[10];
    const float* b_hh   = (const float*)d_in[11];
    const float* out_W  = (const float*)d_in[12];
    const float* out_b  = (const float*)d_in[13];
    float* out = (float*)d_out;   // [0,V): logp ; [V,V+L): attn_weights

    k_attn_gemv<<<64, 256>>>(x, emb, hidden, attn_W, attn_b);
    k_softmax<<<1, 512>>>(out + V);
    k_attn_apply<<<dim3(8, 4), 128>>>(enc);
    k_combine_relu<<<128, 256>>>(x, emb, comb_W, comb_b);
    k_gates_gemv<<<768, 256>>>(hidden, W_ih, W_hh, b_ih, b_hh);
    k_gru<<<4, 256>>>(hidden);
    k_out_gemv<<<(V + 7) / 8, 256>>>(out_W, out_b);
    k_lse_part<<<64, 256>>>();
    k_lse_comb<<<1, 64>>>();
    k_write_logp<<<128, 256>>>(out);
}

// round 2
// speedup vs baseline: 1.2830x; 1.2830x over previous
#include <cuda_runtime.h>
#include <math.h>

#define H 1024
#define V 50257
#define L 512

// ---------------- scratch (device globals; no allocations allowed) ----------
__device__ float g_scores[L];
__device__ float g_attnw[L];
__device__ float g_attn_partial[8][H];
__device__ float g_gru_in[H];
__device__ float g_gates[6 * H];         // [0,3H)=gx, [3H,6H)=gh
__device__ float g_hnew[H];
__device__ float g_logits[V];
__device__ float g_pm[64], g_ps[64];

__device__ __forceinline__ float warp_reduce_sum(float v) {
#pragma unroll
    for (int o = 16; o; o >>= 1) v += __shfl_down_sync(0xffffffffu, v, o);
    return v;
}

// ---- 1) attention scores: scores = attn_W @ [emb[x]; h0] + b ---------------
// 128 blocks x 256 thr; 4 rows/block, 2 warps per row (1024 cols each).
__global__ void k_attn_gemv(const int* __restrict__ x,
                            const float* __restrict__ emb,
                            const float* __restrict__ hidden,
                            const float* __restrict__ attn_W,
                            const float* __restrict__ attn_b) {
    __shared__ float s[2 * H];
    __shared__ float part[8];
    const float* er = emb + (size_t)x[0] * H;
    for (int i = threadIdx.x; i < H; i += 256) {
        s[i] = er[i];
        s[H + i] = hidden[i];
    }
    __syncthreads();
    const int warp = threadIdx.x >> 5, lane = threadIdx.x & 31;
    const int row  = blockIdx.x * 4 + (warp >> 1);
    const int half = warp & 1;
    const float4* Wr = (const float4*)(attn_W + (size_t)row * (2 * H) + half * H);
    const float4* sv = (const float4*)(s + half * H);
    float4 w[8];
#pragma unroll
    for (int i = 0; i < 8; i++) w[i] = Wr[lane + i * 32];
    float acc = 0.f;
#pragma unroll
    for (int i = 0; i < 8; i++) {
        float4 v = sv[lane + i * 32];
        acc += w[i].x * v.x + w[i].y * v.y + w[i].z * v.z + w[i].w * v.w;
    }
    acc = warp_reduce_sum(acc);
    if (lane == 0) part[warp] = acc;
    __syncthreads();
    if (threadIdx.x < 4) {
        const int r = blockIdx.x * 4 + threadIdx.x;
        g_scores[r] = part[2 * threadIdx.x] + part[2 * threadIdx.x + 1] + attn_b[r];
    }
}

// ---- 2) softmax over 512 scores; also writes attn_weights output -----------
__global__ void k_softmax(float* __restrict__ out_attnw) {
    __shared__ float red[L];
    const int t = threadIdx.x;
    float v = g_scores[t];
    red[t] = v;
    __syncthreads();
    for (int o = 256; o; o >>= 1) {
        if (t < o) red[t] = fmaxf(red[t], red[t + o]);
        __syncthreads();
    }
    const float m = red[0];
    __syncthreads();
    float e = expf(v - m);
    red[t] = e;
    __syncthreads();
    for (int o = 256; o; o >>= 1) {
        if (t < o) red[t] += red[t + o];
        __syncthreads();
    }
    float w = e / red[0];
    g_attnw[t] = w;
    out_attnw[t] = w;
}

// ---- 3) attn_applied partials: grid(8 col-tiles, 8 L-chunks of 64) ---------
__global__ void k_attn_apply(const float* __restrict__ enc) {
    __shared__ float sw[64];
    const int j  = blockIdx.x * 128 + threadIdx.x;
    const int l0 = blockIdx.y * 64;
    if (threadIdx.x < 64) sw[threadIdx.x] = g_attnw[l0 + threadIdx.x];
    __syncthreads();
    float acc = 0.f;
#pragma unroll 8
    for (int l = 0; l < 64; l++)
        acc += sw[l] * enc[(size_t)(l0 + l) * H + j];
    g_attn_partial[blockIdx.y][j] = acc;
}

// ---- 4) combine + relu: gru_in = relu(comb_W @ [emb; attn_applied] + b) ----
// 256 blocks x 256 thr; 4 rows/block, 2 warps/row.
__global__ void k_combine_relu(const int* __restrict__ x,
                               const float* __restrict__ emb,
                               const float* __restrict__ comb_W,
                               const float* __restrict__ comb_b) {
    __shared__ float s[2 * H];
    __shared__ float part[8];
    const float* er = emb + (size_t)x[0] * H;
    for (int i = threadIdx.x; i < H; i += 256) {
        s[i] = er[i];
        float a = 0.f;
#pragma unroll
        for (int c = 0; c < 8; c++) a += g_attn_partial[c][i];
        s[H + i] = a;
    }
    __syncthreads();
    const int warp = threadIdx.x >> 5, lane = threadIdx.x & 31;
    const int row  = blockIdx.x * 4 + (warp >> 1);
    const int half = warp & 1;
    const float4* Wr = (const float4*)(comb_W + (size_t)row * (2 * H) + half * H);
    const float4* sv = (const float4*)(s + half * H);
    float4 w[8];
#pragma unroll
    for (int i = 0; i < 8; i++) w[i] = Wr[lane + i * 32];
    float acc = 0.f;
#pragma unroll
    for (int i = 0; i < 8; i++) {
        float4 v = sv[lane + i * 32];
        acc += w[i].x * v.x + w[i].y * v.y + w[i].z * v.z + w[i].w * v.w;
    }
    acc = warp_reduce_sum(acc);
    if (lane == 0) part[warp] = acc;
    __syncthreads();
    if (threadIdx.x < 4) {
        const int r = blockIdx.x * 4 + threadIdx.x;
        g_gru_in[r] = fmaxf(part[2 * threadIdx.x] + part[2 * threadIdx.x + 1] + comb_b[r], 0.f);
    }
}

// ---- 5) GRU gate GEMVs: 6144 rows x 1024, warp-per-row ---------------------
__global__ void k_gates_gemv(const float* __restrict__ hidden,
                             const float* __restrict__ W_ih,
                             const float* __restrict__ W_hh,
                             const float* __restrict__ b_ih,
                             const float* __restrict__ b_hh) {
    __shared__ float s[H];
    const int base = blockIdx.x * 8;
    const bool is_ih = base < 3 * H;
    const float* vec = is_ih ? g_gru_in : hidden;
    for (int i = threadIdx.x; i < H; i += 256) s[i] = vec[i];
    __syncthreads();
    const int warp = threadIdx.x >> 5, lane = threadIdx.x & 31;
    const int row = base + warp;
    const int r = is_ih ? row : row - 3 * H;
    const float* W = is_ih ? W_ih : W_hh;
    const float* b = is_ih ? b_ih : b_hh;
    const float4* Wr = (const float4*)(W + (size_t)r * H);
    const float4* sv = (const float4*)s;
    float4 w[8];
#pragma unroll
    for (int i = 0; i < 8; i++) w[i] = Wr[lane + i * 32];
    float acc = 0.f;
#pragma unroll
    for (int i = 0; i < 8; i++) {
        float4 v = sv[lane + i * 32];
        acc += w[i].x * v.x + w[i].y * v.y + w[i].z * v.z + w[i].w * v.w;
    }
    acc = warp_reduce_sum(acc);
    if (lane == 0) g_gates[row] = acc + b[r];
}

// ---- 6) GRU elementwise ----------------------------------------------------
__global__ void k_gru(const float* __restrict__ hidden) {
    const int i = blockIdx.x * 256 + threadIdx.x;
    const float gxr = g_gates[i],         ghr = g_gates[3 * H + i];
    const float gxz = g_gates[H + i],     ghz = g_gates[4 * H + i];
    const float gxn = g_gates[2 * H + i], ghn = g_gates[5 * H + i];
    const float r = 1.f / (1.f + expf(-(gxr + ghr)));
    const float z = 1.f / (1.f + expf(-(gxz + ghz)));
    const float n = tanhf(gxn + r * ghn);
    g_hnew[i] = (1.f - z) * n + z * hidden[i];
}

// ---- 7) big GEMV: logits = out_W @ h_new + out_b (206 MB stream) -----------
__global__ void k_out_gemv(const float* __restrict__ out_W,
                           const float* __restrict__ out_b) {
    __shared__ float s[H];
    for (int i = threadIdx.x; i < H; i += 256) s[i] = g_hnew[i];
    __syncthreads();
    const int warp = threadIdx.x >> 5, lane = threadIdx.x & 31;
    const int row = blockIdx.x * 8 + warp;
    if (row >= V) return;
    const float4* Wr = (const float4*)(out_W + (size_t)row * H);
    const float4* sv = (const float4*)s;
    float4 w[8];
#pragma unroll
    for (int i = 0; i < 8; i++) w[i] = Wr[lane + i * 32];
    float acc = 0.f;
#pragma unroll
    for (int i = 0; i < 8; i++) {
        float4 v = sv[lane + i * 32];
        acc += w[i].x * v.x + w[i].y * v.y + w[i].z * v.z + w[i].w * v.w;
    }
    acc = warp_reduce_sum(acc);
    if (lane == 0) g_logits[row] = acc + out_b[row];
}

// ---- 8) log-sum-exp partials (online, deterministic) -----------------------
__global__ void k_lse_part() {
    __shared__ float sm[256], ss[256];
    const int t = threadIdx.x;
    const int g0 = blockIdx.x * 256 + t;
    float m = -INFINITY, s = 0.f;
    for (int v = g0; v < V; v += 64 * 256) {
        const float xv = g_logits[v];
        const float nm = fmaxf(m, xv);
        s = s * expf(m - nm) + expf(xv - nm);
        m = nm;
    }
    sm[t] = m; ss[t] = s;
    __syncthreads();
    for (int o = 128; o; o >>= 1) {
        if (t < o) {
            const float m2 = sm[t + o], s2 = ss[t + o];
            const float nm = fmaxf(sm[t], m2);
            ss[t] = ss[t] * expf(sm[t] - nm) + s2 * expf(m2 - nm);
            sm[t] = nm;
        }
        __syncthreads();
    }
    if (t == 0) { g_pm[blockIdx.x] = sm[0]; g_ps[blockIdx.x] = ss[0]; }
}

// ---- 9) write log-probs; every block redundantly combines the 64 partials
//         with the SAME tree (deterministic, saves one kernel launch) --------
__global__ void k_write_logp(float* __restrict__ out) {
    __shared__ float sm[64], ss[64];
    if (threadIdx.x < 64) { sm[threadIdx.x] = g_pm[threadIdx.x]; ss[threadIdx.x] = g_ps[threadIdx.x]; }
    __syncthreads();
    for (int o = 32; o; o >>= 1) {
        if (threadIdx.x < o) {
            const float m2 = sm[threadIdx.x + o], s2 = ss[threadIdx.x + o];
            const float nm = fmaxf(sm[threadIdx.x], m2);
            ss[threadIdx.x] = ss[threadIdx.x] * expf(sm[threadIdx.x] - nm) + s2 * expf(m2 - nm);
            sm[threadIdx.x] = nm;
        }
        __syncthreads();
    }
    const float lse = sm[0] + logf(ss[0]);
    for (int v = blockIdx.x * 256 + threadIdx.x; v < V; v += gridDim.x * 256)
        out[v] = g_logits[v] - lse;
}

extern "C" void kernel_launch(void* const* d_in, const int* in_sizes, int n_in,
                              void* d_out, int out_size) {
    const int*   x      = (const int*)  d_in[0];
    const float* enc    = (const float*)d_in[1];
    const float* hidden = (const float*)d_in[2];
    const float* emb    = (const float*)d_in[3];
    const float* attn_W = (const float*)d_in[4];
    const float* attn_b = (const float*)d_in[5];
    const float* comb_W = (const float*)d_in[6];
    const float* comb_b = (const float*)d_in[7];
    const float* W_ih   = (const float*)d_in[8];
    const float* W_hh   = (const float*)d_in[9];
    const float* b_ih   = (const float*)d_in[10];
    const float* b_hh   = (const float*)d_in[11];
    const float* out_W  = (const float*)d_in[12];
    const float* out_b  = (const float*)d_in[13];
    float* out = (float*)d_out;   // [0,V): logp ; [V,V+L): attn_weights

    k_attn_gemv<<<128, 256>>>(x, emb, hidden, attn_W, attn_b);
    k_softmax<<<1, 512>>>(out + V);
    k_attn_apply<<<dim3(8, 8), 128>>>(enc);
    k_combine_relu<<<256, 256>>>(x, emb, comb_W, comb_b);
    k_gates_gemv<<<768, 256>>>(hidden, W_ih, W_hh, b_ih, b_hh);
    k_gru<<<4, 256>>>(hidden);
    k_out_gemv<<<(V + 7) / 8, 256>>>(out_W, out_b);
    k_lse_part<<<64, 256>>>();
    k_write_logp<<<128, 256>>>(out);
}

// round 3
// speedup vs baseline: 1.3216x; 1.0301x over previous
#include <cuda_runtime.h>
#include <math.h>

#define H 1024
#define V 50257
#define L 512

// ---------------- scratch (device globals; no allocations allowed) ----------
__device__ float g_scores[L];
__device__ float g_attnw[L];
__device__ float g_attn_partial[8][H];
__device__ float g_gru_in[H];
__device__ float g_gates[6 * H];         // [0,3H)=gx, [3H,6H)=gh
__device__ float g_hnew[H];
__device__ float g_logits[V];
__device__ float g_pm[64], g_ps[64];

__device__ __forceinline__ float warp_reduce_sum(float v) {
#pragma unroll
    for (int o = 16; o; o >>= 1) v += __shfl_down_sync(0xffffffffu, v, o);
    return v;
}

// Forced-order vector load: volatile asm pins all loads in program order so
// ptxas cannot re-pair them with FMAs (keeps MLP = #loads emitted).
__device__ __forceinline__ float4 ldg4(const float4* p) {
    float4 v;
    asm volatile("ld.global.nc.v4.f32 {%0,%1,%2,%3},[%4];"
                 : "=f"(v.x), "=f"(v.y), "=f"(v.z), "=f"(v.w) : "l"(p));
    return v;
}

// ---- 1) attention scores: scores = attn_W @ [emb[x]; h0] + b ---------------
// 128 blocks x 256 thr; 4 rows/block, 2 warps per row (1024 cols each).
__global__ void k_attn_gemv(const int* __restrict__ x,
                            const float* __restrict__ emb,
                            const float* __restrict__ hidden,
                            const float* __restrict__ attn_W,
                            const float* __restrict__ attn_b) {
    __shared__ float s[2 * H];
    __shared__ float part[8];
    const float* er = emb + (size_t)x[0] * H;
    for (int i = threadIdx.x; i < H; i += 256) {
        s[i] = er[i];
        s[H + i] = hidden[i];
    }
    __syncthreads();
    const int warp = threadIdx.x >> 5, lane = threadIdx.x & 31;
    const int row  = blockIdx.x * 4 + (warp >> 1);
    const int half = warp & 1;
    const float4* Wr = (const float4*)(attn_W + (size_t)row * (2 * H) + half * H);
    const float4* sv = (const float4*)(s + half * H);
    float4 w[8];
#pragma unroll
    for (int i = 0; i < 8; i++) w[i] = ldg4(Wr + lane + i * 32);
    float acc = 0.f;
#pragma unroll
    for (int i = 0; i < 8; i++) {
        float4 v = sv[lane + i * 32];
        acc += w[i].x * v.x + w[i].y * v.y + w[i].z * v.z + w[i].w * v.w;
    }
    acc = warp_reduce_sum(acc);
    if (lane == 0) part[warp] = acc;
    __syncthreads();
    if (threadIdx.x < 4) {
        const int r = blockIdx.x * 4 + threadIdx.x;
        g_scores[r] = part[2 * threadIdx.x] + part[2 * threadIdx.x + 1] + attn_b[r];
    }
}

// ---- 2) softmax over 512 scores; also writes attn_weights output -----------
__global__ void k_softmax(float* __restrict__ out_attnw) {
    __shared__ float red[L];
    const int t = threadIdx.x;
    float v = g_scores[t];
    red[t] = v;
    __syncthreads();
    for (int o = 256; o; o >>= 1) {
        if (t < o) red[t] = fmaxf(red[t], red[t + o]);
        __syncthreads();
    }
    const float m = red[0];
    __syncthreads();
    float e = expf(v - m);
    red[t] = e;
    __syncthreads();
    for (int o = 256; o; o >>= 1) {
        if (t < o) red[t] += red[t + o];
        __syncthreads();
    }
    float w = e / red[0];
    g_attnw[t] = w;
    out_attnw[t] = w;
}

// ---- 3) attn_applied partials: grid(8 col-tiles, 8 L-chunks of 64) ---------
__global__ void k_attn_apply(const float* __restrict__ enc) {
    __shared__ float sw[64];
    const int j  = blockIdx.x * 128 + threadIdx.x;
    const int l0 = blockIdx.y * 64;
    if (threadIdx.x < 64) sw[threadIdx.x] = g_attnw[l0 + threadIdx.x];
    __syncthreads();
    float acc = 0.f;
    // batches of 8 forced loads, then 8 FMAs
    for (int lb = 0; lb < 64; lb += 8) {
        float e[8];
#pragma unroll
        for (int u = 0; u < 8; u++)
            asm volatile("ld.global.nc.f32 %0,[%1];" : "=f"(e[u])
                         : "l"(enc + (size_t)(l0 + lb + u) * H + j));
#pragma unroll
        for (int u = 0; u < 8; u++) acc += sw[lb + u] * e[u];
    }
    g_attn_partial[blockIdx.y][j] = acc;
}

// ---- 4) combine + relu: gru_in = relu(comb_W @ [emb; attn_applied] + b) ----
// 256 blocks x 256 thr; 4 rows/block, 2 warps/row.
__global__ void k_combine_relu(const int* __restrict__ x,
                               const float* __restrict__ emb,
                               const float* __restrict__ comb_W,
                               const float* __restrict__ comb_b) {
    __shared__ float s[2 * H];
    __shared__ float part[8];
    const float* er = emb + (size_t)x[0] * H;
    for (int i = threadIdx.x; i < H; i += 256) {
        s[i] = er[i];
        float a = 0.f;
#pragma unroll
        for (int c = 0; c < 8; c++) a += g_attn_partial[c][i];
        s[H + i] = a;
    }
    __syncthreads();
    const int warp = threadIdx.x >> 5, lane = threadIdx.x & 31;
    const int row  = blockIdx.x * 4 + (warp >> 1);
    const int half = warp & 1;
    const float4* Wr = (const float4*)(comb_W + (size_t)row * (2 * H) + half * H);
    const float4* sv = (const float4*)(s + half * H);
    float4 w[8];
#pragma unroll
    for (int i = 0; i < 8; i++) w[i] = ldg4(Wr + lane + i * 32);
    float acc = 0.f;
#pragma unroll
    for (int i = 0; i < 8; i++) {
        float4 v = sv[lane + i * 32];
        acc += w[i].x * v.x + w[i].y * v.y + w[i].z * v.z + w[i].w * v.w;
    }
    acc = warp_reduce_sum(acc);
    if (lane == 0) part[warp] = acc;
    __syncthreads();
    if (threadIdx.x < 4) {
        const int r = blockIdx.x * 4 + threadIdx.x;
        g_gru_in[r] = fmaxf(part[2 * threadIdx.x] + part[2 * threadIdx.x + 1] + comb_b[r], 0.f);
    }
}

// ---- 5) GRU gate GEMVs: 6144 rows x 1024, warp-per-row ---------------------
__global__ void k_gates_gemv(const float* __restrict__ hidden,
                             const float* __restrict__ W_ih,
                             const float* __restrict__ W_hh,
                             const float* __restrict__ b_ih,
                             const float* __restrict__ b_hh) {
    __shared__ float s[H];
    const int base = blockIdx.x * 8;
    const bool is_ih = base < 3 * H;
    const float* vec = is_ih ? g_gru_in : hidden;
    for (int i = threadIdx.x; i < H; i += 256) s[i] = vec[i];
    __syncthreads();
    const int warp = threadIdx.x >> 5, lane = threadIdx.x & 31;
    const int row = base + warp;
    const int r = is_ih ? row : row - 3 * H;
    const float* W = is_ih ? W_ih : W_hh;
    const float* b = is_ih ? b_ih : b_hh;
    const float4* Wr = (const float4*)(W + (size_t)r * H);
    const float4* sv = (const float4*)s;
    float4 w[8];
#pragma unroll
    for (int i = 0; i < 8; i++) w[i] = ldg4(Wr + lane + i * 32);
    float acc = 0.f;
#pragma unroll
    for (int i = 0; i < 8; i++) {
        float4 v = sv[lane + i * 32];
        acc += w[i].x * v.x + w[i].y * v.y + w[i].z * v.z + w[i].w * v.w;
    }
    acc = warp_reduce_sum(acc);
    if (lane == 0) g_gates[row] = acc + b[r];
}

// ---- 6) GRU elementwise ----------------------------------------------------
__global__ void k_gru(const float* __restrict__ hidden) {
    const int i = blockIdx.x * 256 + threadIdx.x;
    const float gxr = g_gates[i],         ghr = g_gates[3 * H + i];
    const float gxz = g_gates[H + i],     ghz = g_gates[4 * H + i];
    const float gxn = g_gates[2 * H + i], ghn = g_gates[5 * H + i];
    const float r = 1.f / (1.f + expf(-(gxr + ghr)));
    const float z = 1.f / (1.f + expf(-(gxz + ghz)));
    const float n = tanhf(gxn + r * ghn);
    g_hnew[i] = (1.f - z) * n + z * hidden[i];
}

// ---- 7) big GEMV: logits = out_W @ h_new + out_b (206 MB stream) -----------
__global__ void k_out_gemv(const float* __restrict__ out_W,
                           const float* __restrict__ out_b) {
    __shared__ float s[H];
    for (int i = threadIdx.x; i < H; i += 256) s[i] = g_hnew[i];
    __syncthreads();
    const int warp = threadIdx.x >> 5, lane = threadIdx.x & 31;
    const int row = blockIdx.x * 8 + warp;
    if (row >= V) return;
    const float4* Wr = (const float4*)(out_W + (size_t)row * H);
    const float4* sv = (const float4*)s;
    float4 w[8];
#pragma unroll
    for (int i = 0; i < 8; i++) w[i] = ldg4(Wr + lane + i * 32);
    float acc = 0.f;
#pragma unroll
    for (int i = 0; i < 8; i++) {
        float4 v = sv[lane + i * 32];
        acc += w[i].x * v.x + w[i].y * v.y + w[i].z * v.z + w[i].w * v.w;
    }
    acc = warp_reduce_sum(acc);
    if (lane == 0) g_logits[row] = acc + out_b[row];
}

// ---- 8) log-sum-exp partials (online, deterministic) -----------------------
__global__ void k_lse_part() {
    __shared__ float sm[256], ss[256];
    const int t = threadIdx.x;
    const int g0 = blockIdx.x * 256 + t;
    float m = -INFINITY, s = 0.f;
    for (int v = g0; v < V; v += 64 * 256) {
        const float xv = g_logits[v];
        const float nm = fmaxf(m, xv);
        s = s * expf(m - nm) + expf(xv - nm);
        m = nm;
    }
    sm[t] = m; ss[t] = s;
    __syncthreads();
    for (int o = 128; o; o >>= 1) {
        if (t < o) {
            const float m2 = sm[t + o], s2 = ss[t + o];
            const float nm = fmaxf(sm[t], m2);
            ss[t] = ss[t] * expf(sm[t] - nm) + s2 * expf(m2 - nm);
            sm[t] = nm;
        }
        __syncthreads();
    }
    if (t == 0) { g_pm[blockIdx.x] = sm[0]; g_ps[blockIdx.x] = ss[0]; }
}

// ---- 9) write log-probs; every block redundantly combines the 64 partials
//         with the SAME tree (deterministic, saves one kernel launch) --------
__global__ void k_write_logp(float* __restrict__ out) {
    __shared__ float sm[64], ss[64];
    if (threadIdx.x < 64) { sm[threadIdx.x] = g_pm[threadIdx.x]; ss[threadIdx.x] = g_ps[threadIdx.x]; }
    __syncthreads();
    for (int o = 32; o; o >>= 1) {
        if (threadIdx.x < o) {
            const float m2 = sm[threadIdx.x + o], s2 = ss[threadIdx.x + o];
            const float nm = fmaxf(sm[threadIdx.x], m2);
            ss[threadIdx.x] = ss[threadIdx.x] * expf(sm[threadIdx.x] - nm) + s2 * expf(m2 - nm);
            sm[threadIdx.x] = nm;
        }
        __syncthreads();
    }
    const float lse = sm[0] + logf(ss[0]);
    for (int v = blockIdx.x * 256 + threadIdx.x; v < V; v += gridDim.x * 256)
        out[v] = g_logits[v] - lse;
}

extern "C" void kernel_launch(void* const* d_in, const int* in_sizes, int n_in,
                              void* d_out, int out_size) {
    const int*   x      = (const int*)  d_in[0];
    const float* enc    = (const float*)d_in[1];
    const float* hidden = (const float*)d_in[2];
    const float* emb    = (const float*)d_in[3];
    const float* attn_W = (const float*)d_in[4];
    const float* attn_b = (const float*)d_in[5];
    const float* comb_W = (const float*)d_in[6];
    const float* comb_b = (const float*)d_in[7];
    const float* W_ih   = (const float*)d_in[8];
    const float* W_hh   = (const float*)d_in[9];
    const float* b_ih   = (const float*)d_in[10];
    const float* b_hh   = (const float*)d_in[11];
    const float* out_W  = (const float*)d_in[12];
    const float* out_b  = (const float*)d_in[13];
    float* out = (float*)d_out;   // [0,V): logp ; [V,V+L): attn_weights

    k_attn_gemv<<<128, 256>>>(x, emb, hidden, attn_W, attn_b);
    k_softmax<<<1, 512>>>(out + V);
    k_attn_apply<<<dim3(8, 8), 128>>>(enc);
    k_combine_relu<<<256, 256>>>(x, emb, comb_W, comb_b);
    k_gates_gemv<<<768, 256>>>(hidden, W_ih, W_hh, b_ih, b_hh);
    k_gru<<<4, 256>>>(hidden);
    k_out_gemv<<<(V + 7) / 8, 256>>>(out_W, out_b);
    k_lse_part<<<64, 256>>>();
    k_write_logp<<<128, 256>>>(out);
}

// round 4
// speedup vs baseline: 1.4175x; 1.0726x over previous
#include <cuda_runtime.h>
#include <math.h>

#define H 1024
#define V 50257
#define L 512
#define GRID 148
#define TPB 1024
#define ROWS_PB 340      // ceil(V / GRID)

// ---------------- scratch (device globals; no allocations allowed) ----------
__device__ float g_scores[L];
__device__ float g_attnw[L];
__device__ float g_attn_partial[8][H];
__device__ float g_gru_in[H];
__device__ float g_gates[6 * H];
__device__ float g_hnew[H];
__device__ float g_logits[V];
__device__ float g_pm[GRID], g_ps[GRID];
__device__ unsigned g_bars[8];

__global__ void k_reset() {
    if (threadIdx.x < 8) g_bars[threadIdx.x] = 0u;
}

__device__ __forceinline__ float4 ldg4(const float4* p) {
    float4 v;
    asm volatile("ld.global.nc.v4.f32 {%0,%1,%2,%3},[%4];"
                 : "=f"(v.x), "=f"(v.y), "=f"(v.z), "=f"(v.w) : "l"(p));
    return v;
}
__device__ __forceinline__ float ldg1(const float* p) {
    float v;
    asm volatile("ld.global.nc.f32 %0,[%1];" : "=f"(v) : "l"(p));
    return v;
}
__device__ __forceinline__ float wsum(float v) {
#pragma unroll
    for (int o = 16; o; o >>= 1) v += __shfl_down_sync(0xffffffffu, v, o);
    return v;
}

// software grid barrier: all 148 CTAs resident (1 CTA/SM) so spin is safe.
__device__ __forceinline__ void gbar(int ph) {
    __syncthreads();
    if (threadIdx.x == 0) {
        __threadfence();
        atomicAdd(&g_bars[ph], 1u);
        volatile unsigned* p = &g_bars[ph];
        while (*p < GRID) { }
        __threadfence();
    }
    __syncthreads();
}

__global__ void __launch_bounds__(TPB, 1)
k_fused(const int* __restrict__ x,
        const float* __restrict__ enc,
        const float* __restrict__ hidden,
        const float* __restrict__ emb,
        const float* __restrict__ attn_W,
        const float* __restrict__ attn_b,
        const float* __restrict__ comb_W,
        const float* __restrict__ comb_b,
        const float* __restrict__ W_ih,
        const float* __restrict__ W_hh,
        const float* __restrict__ b_ih,
        const float* __restrict__ b_hh,
        const float* __restrict__ out_W,
        const float* __restrict__ out_b,
        float* __restrict__ out) {
    __shared__ float s_emb[H];
    __shared__ float s_h0[H];
    __shared__ float s_vec[H];
    __shared__ float red[1024];
    __shared__ float wm[32], ws[32];

    const int t = threadIdx.x, b = blockIdx.x;
    const int wid = t >> 5, lane = t & 31;

    // preload emb row + hidden into shared (reused across phases)
    {
        const float* er = emb + (size_t)x[0] * H;
        for (int i = t; i < H; i += TPB) { s_emb[i] = er[i]; s_h0[i] = hidden[i]; }
        __syncthreads();
    }

    // ---- P1: attention scores (blocks 0..63; 8 rows/block, 4 warps/row) ----
    if (b < 64) {
        const int row = b * 8 + (wid >> 2), q = wid & 3;
        const float* vp = (q < 2) ? (s_emb + q * 512) : (s_h0 + (q - 2) * 512);
        const float4* Wr = (const float4*)(attn_W + (size_t)row * (2 * H) + q * 512);
        const float4* sv = (const float4*)vp;
        float4 w[4];
#pragma unroll
        for (int i = 0; i < 4; i++) w[i] = ldg4(Wr + lane + i * 32);
        float acc = 0.f;
#pragma unroll
        for (int i = 0; i < 4; i++) {
            float4 v = sv[lane + i * 32];
            acc += w[i].x * v.x + w[i].y * v.y + w[i].z * v.z + w[i].w * v.w;
        }
        acc = wsum(acc);
        if (lane == 0) red[wid] = acc;
        __syncthreads();
        if (t < 8) {
            const int r = b * 8 + t;
            g_scores[r] = red[4 * t] + red[4 * t + 1] + red[4 * t + 2] + red[4 * t + 3] + attn_b[r];
        }
    }
    gbar(0);

    // ---- P2: softmax over 512 scores (block 0); writes attn_weights out ----
    if (b == 0) {
        float v = (t < L) ? g_scores[t] : -INFINITY;
        red[t] = v;
        __syncthreads();
        for (int o = 512; o; o >>= 1) {
            if (t < o) red[t] = fmaxf(red[t], red[t + o]);
            __syncthreads();
        }
        const float m = red[0];
        __syncthreads();
        float e = (t < L) ? expf(v - m) : 0.f;
        red[t] = e;
        __syncthreads();
        for (int o = 512; o; o >>= 1) {
            if (t < o) red[t] += red[t + o];
            __syncthreads();
        }
        if (t < L) {
            const float w = e / red[0];
            g_attnw[t] = w;
            out[V + t] = w;
        }
    }
    gbar(1);

    // ---- P3: attn_applied partials (blocks 0..63) --------------------------
    if (b < 64) {
        const int lc = b >> 3, jc = b & 7;
        const int j = jc * 128 + (t & 127);
        const int sub = t >> 7;                 // 0..7
        const int l0 = lc * 64 + sub * 8;
        float e[8];
#pragma unroll
        for (int u = 0; u < 8; u++) e[u] = ldg1(enc + (size_t)(l0 + u) * H + j);
        float acc = 0.f;
#pragma unroll
        for (int u = 0; u < 8; u++) acc += g_attnw[l0 + u] * e[u];
        red[t] = acc;
        __syncthreads();
        for (int o = 512; o >= 128; o >>= 1) {
            if (t < o) red[t] += red[t + o];
            __syncthreads();
        }
        if (t < 128) g_attn_partial[lc][jc * 128 + t] = red[t];
    }
    gbar(2);

    // ---- P4: combine + relu (blocks 0..127; 8 rows/block, 4 warps/row) ----
    if (b < 128) {
        for (int i = t; i < H; i += TPB) {
            float a = 0.f;
#pragma unroll
            for (int c = 0; c < 8; c++) a += g_attn_partial[c][i];
            s_vec[i] = a;
        }
        __syncthreads();
        const int row = b * 8 + (wid >> 2), q = wid & 3;
        const float* vp = (q < 2) ? (s_emb + q * 512) : (s_vec + (q - 2) * 512);
        const float4* Wr = (const float4*)(comb_W + (size_t)row * (2 * H) + q * 512);
        const float4* sv = (const float4*)vp;
        float4 w[4];
#pragma unroll
        for (int i = 0; i < 4; i++) w[i] = ldg4(Wr + lane + i * 32);
        float acc = 0.f;
#pragma unroll
        for (int i = 0; i < 4; i++) {
            float4 v = sv[lane + i * 32];
            acc += w[i].x * v.x + w[i].y * v.y + w[i].z * v.z + w[i].w * v.w;
        }
        acc = wsum(acc);
        if (lane == 0) red[wid] = acc;
        __syncthreads();
        if (t < 8) {
            const int r = b * 8 + t;
            g_gru_in[r] = fmaxf(red[4 * t] + red[4 * t + 1] + red[4 * t + 2] + red[4 * t + 3] + comb_b[r], 0.f);
        }
    }
    gbar(3);

    // ---- P5: GRU gate GEMVs (6144 rows x 1024; warp-per-row, all blocks) ---
    for (int i = t; i < H; i += TPB) s_vec[i] = g_gru_in[i];
    __syncthreads();
    {
        const int gw = b * 32 + wid;
        for (int job = gw; job < 6 * H; job += GRID * 32) {
            const bool ih = job < 3 * H;
            const int r = ih ? job : job - 3 * H;
            const float* W = ih ? W_ih : W_hh;
            const float* bb = ih ? b_ih : b_hh;
            const float* vp = ih ? s_vec : s_h0;
            const float4* Wr = (const float4*)(W + (size_t)r * H);
            const float4* sv = (const float4*)vp;
            float4 w[8];
#pragma unroll
            for (int i = 0; i < 8; i++) w[i] = ldg4(Wr + lane + i * 32);
            float acc = 0.f;
#pragma unroll
            for (int i = 0; i < 8; i++) {
                float4 v = sv[lane + i * 32];
                acc += w[i].x * v.x + w[i].y * v.y + w[i].z * v.z + w[i].w * v.w;
            }
            acc = wsum(acc);
            if (lane == 0) g_gates[job] = acc + bb[r];
        }
    }
    gbar(4);

    // ---- P6: GRU elementwise (block 0, 1024 threads) -----------------------
    if (b == 0) {
        const int i = t;
        const float gxr = g_gates[i],         ghr = g_gates[3 * H + i];
        const float gxz = g_gates[H + i],     ghz = g_gates[4 * H + i];
        const float gxn = g_gates[2 * H + i], ghn = g_gates[5 * H + i];
        const float r = 1.f / (1.f + expf(-(gxr + ghr)));
        const float z = 1.f / (1.f + expf(-(gxz + ghz)));
        const float n = tanhf(gxn + r * ghn);
        g_hnew[i] = (1.f - z) * n + z * s_h0[i];
    }
    gbar(5);

    // ---- P7: big GEMV + per-block online LSE partial -----------------------
    for (int i = t; i < H; i += TPB) s_vec[i] = g_hnew[i];
    __syncthreads();
    const int r0 = b * ROWS_PB;
    const int r1 = (r0 + ROWS_PB < V) ? (r0 + ROWS_PB) : V;
    {
        float m = -INFINITY, s = 0.f;
        for (int r = r0 + wid; r < r1; r += 32) {
            const float4* Wr = (const float4*)(out_W + (size_t)r * H);
            const float4* sv = (const float4*)s_vec;
            float4 w[8];
#pragma unroll
            for (int i = 0; i < 8; i++) w[i] = ldg4(Wr + lane + i * 32);
            float acc = 0.f;
#pragma unroll
            for (int i = 0; i < 8; i++) {
                float4 v = sv[lane + i * 32];
                acc += w[i].x * v.x + w[i].y * v.y + w[i].z * v.z + w[i].w * v.w;
            }
            acc = wsum(acc);
            if (lane == 0) {
                const float lg = acc + out_b[r];
                g_logits[r] = lg;
                const float nm = fmaxf(m, lg);
                s = s * expf(m - nm) + expf(lg - nm);
                m = nm;
            }
        }
        if (lane == 0) { wm[wid] = m; ws[wid] = s; }
        __syncthreads();
        for (int o = 16; o; o >>= 1) {
            if (t < o) {
                const float m2 = wm[t + o], s2 = ws[t + o];
                const float nm = fmaxf(wm[t], m2);
                ws[t] = ws[t] * expf(wm[t] - nm) + s2 * expf(m2 - nm);
                wm[t] = nm;
            }
            __syncthreads();
        }
        if (t == 0) { g_pm[b] = wm[0]; g_ps[b] = ws[0]; }
    }
    gbar(6);

    // ---- P8: every block combines 148 partials identically, writes logp ----
    {
        if (t < 256) {
            red[t]       = (t < GRID) ? g_pm[t] : -INFINITY;
            red[256 + t] = (t < GRID) ? g_ps[t] : 0.f;
        }
        __syncthreads();
        for (int o = 128; o; o >>= 1) {
            if (t < o) {
                const float m2 = red[t + o], s2 = red[256 + t + o];
                const float nm = fmaxf(red[t], m2);
                red[256 + t] = red[256 + t] * expf(red[t] - nm) + s2 * expf(m2 - nm);
                red[t] = nm;
            }
            __syncthreads();
        }
        const float lse = red[0] + logf(red[256]);
        for (int v = r0 + t; v < r1; v += TPB) out[v] = g_logits[v] - lse;
    }
}

extern "C" void kernel_launch(void* const* d_in, const int* in_sizes, int n_in,
                              void* d_out, int out_size) {
    const int*   x      = (const int*)  d_in[0];
    const float* enc    = (const float*)d_in[1];
    const float* hidden = (const float*)d_in[2];
    const float* emb    = (const float*)d_in[3];
    const float* attn_W = (const float*)d_in[4];
    const float* attn_b = (const float*)d_in[5];
    const float* comb_W = (const float*)d_in[6];
    const float* comb_b = (const float*)d_in[7];
    const float* W_ih   = (const float*)d_in[8];
    const float* W_hh   = (const float*)d_in[9];
    const float* b_ih   = (const float*)d_in[10];
    const float* b_hh   = (const float*)d_in[11];
    const float* out_W  = (const float*)d_in[12];
    const float* out_b  = (const float*)d_in[13];
    float* out = (float*)d_out;   // [0,V): logp ; [V,V+L): attn_weights

    k_reset<<<1, 32>>>();
    k_fused<<<GRID, TPB>>>(x, enc, hidden, emb, attn_W, attn_b, comb_W, comb_b,
                           W_ih, W_hh, b_ih, b_hh, out_W, out_b, out);
}